// round 9
// baseline (speedup 1.0000x reference)
#include <cuda_runtime.h>
#include <cuda_fp16.h>

#define NN 100000
#define EE 1600000
#define HID 128
#define EPSV 1e-5f
#define SCAN_T 1024
#define SCAN_CH 98   /* 1024*98 = 100352 >= NN */

typedef unsigned long long u64;
typedef unsigned int u32;

// Scratch (no cudaMalloc allowed).
__device__ __half g_hh[NN * HID];  // GEMM output h (fp16 for cheap gathers)
__device__ float  g_acc[NN * HID]; // aggregation output (fp32)
__device__ int    g_deg[NN];       // zero-init at load; re-zeroed by scan_k each run
__device__ int    g_off[NN + 1];
__device__ int    g_cur[NN];
__device__ int    g_adj[EE];

// ---------------------------------------------------------------------------
// f32x2 helpers
// ---------------------------------------------------------------------------
__device__ __forceinline__ void fma2(u64& d, u64 a, u64 b) {
    asm("fma.rn.f32x2 %0, %1, %2, %0;" : "+l"(d) : "l"(a), "l"(b));
}
__device__ __forceinline__ u64 packf2(float lo, float hi) {
    return (u64)__float_as_uint(lo) | ((u64)__float_as_uint(hi) << 32);
}
__device__ __forceinline__ float sum2(u64 p) {
    return __uint_as_float((u32)p) + __uint_as_float((u32)(p >> 32));
}

// ---------------------------------------------------------------------------
// CSR build (deg starts zeroed; scan re-zeroes it for the next replay)
// ---------------------------------------------------------------------------
__global__ void deg_k(const int* __restrict__ dst, int* deg) {
    int e = blockIdx.x * blockDim.x + threadIdx.x;
    if (e < EE) atomicAdd(&deg[dst[e]], 1);
}

__global__ void __launch_bounds__(SCAN_T) scan_k(int* __restrict__ deg,
                                                 int* __restrict__ off,
                                                 int* __restrict__ cur) {
    __shared__ int sh[SCAN_T];
    int t = threadIdx.x;
    int lo = t * SCAN_CH;
    int hi = min(lo + SCAN_CH, NN);
    int s = 0;
    for (int i = lo; i < hi; i++) s += deg[i];
    sh[t] = s;
    __syncthreads();
    for (int d = 1; d < SCAN_T; d <<= 1) {
        int v = (t >= d) ? sh[t - d] : 0;
        __syncthreads();
        sh[t] += v;
        __syncthreads();
    }
    int base = (t == 0) ? 0 : sh[t - 1];
    for (int i = lo; i < hi; i++) {
        off[i] = base;
        cur[i] = base;
        base += deg[i];
        deg[i] = 0;        // reset for next graph replay
    }
    if (t == SCAN_T - 1) off[NN] = sh[SCAN_T - 1];
}

__global__ void fill_k(const int* __restrict__ src, const int* __restrict__ dst,
                       int* __restrict__ cur, int* __restrict__ adj) {
    int e = blockIdx.x * blockDim.x + threadIdx.x;
    if (e >= EE) return;
    int d = dst[e];
    int p = atomicAdd(&cur[d], 1);
    adj[p] = src[e];
}

// ---------------------------------------------------------------------------
// GEMM: out[N x C] = f(X)[N x 128] @ W[128 x C] + bias
// f32x2 inner loop; W pre-packed k-pairs in smem; x via LDS.128 (2 k-pairs).
//   BNIN: f(x_row) = relu((x_row / (deg+1)) * scale + shift)
//   CLS:  compute h @ Wc2 + bc2 -> outf [N x 2] (fp32)
//   else: store h as fp16 into outh
// ---------------------------------------------------------------------------
template <int C, bool RELU, bool BNIN, bool CLS>
__global__ void __launch_bounds__(256) gemm_k(const float* __restrict__ X,
                                              const float* __restrict__ W,
                                              const float* __restrict__ bias,
                                              __half* __restrict__ outh,
                                              float* __restrict__ outf,
                                              const int* __restrict__ off,
                                              const float* __restrict__ g,
                                              const float* __restrict__ be,
                                              const float* __restrict__ m,
                                              const float* __restrict__ v,
                                              const float* __restrict__ Wc2,
                                              const float* __restrict__ bc2) {
    constexpr int CG  = C / 4;
    constexpr int RT  = 256 / CG;
    constexpr int RPT = (C == 128) ? 8 : 4;
    constexpr int BM  = RT * RPT;       // 64

    extern __shared__ char smraw[];
    float* xs = (float*)smraw;                                   // BM*128 f32
    u64*   ws = (u64*)(smraw + BM * 128 * sizeof(float));        // 64*C u64
    float* sc = (float*)(smraw + BM * 128 * 4 + 64 * C * 8);     // 128 f32
    float* sh = sc + 128;

    const int row0 = blockIdx.x * BM;
    const int nrow = min(BM, NN - row0);

    if (BNIN && threadIdx.x < 128) {
        float s = rsqrtf(v[threadIdx.x] + EPSV) * g[threadIdx.x];
        sc[threadIdx.x] = s;
        sh[threadIdx.x] = be[threadIdx.x] - m[threadIdx.x] * s;
    }

    for (int idx = threadIdx.x; idx < 64 * C; idx += 256) {
        int kk = idx / C, col = idx % C;
        ws[idx] = packf2(__ldg(&W[(2 * kk) * C + col]), __ldg(&W[(2 * kk + 1) * C + col]));
    }

    if (BNIN) __syncthreads();

    {
        const float4* Xv = reinterpret_cast<const float4*>(X + (size_t)row0 * 128);
        float4* xsv = reinterpret_cast<float4*>(xs);
        for (int i = threadIdx.x; i < nrow * 32; i += 256) {
            float4 a = Xv[i];
            if (BNIN) {
                int r = i >> 5;
                int c = (i & 31) * 4;
                int row = row0 + r;
                float ic = 1.0f / (float)(1 + __ldg(&off[row + 1]) - __ldg(&off[row]));
                a.x = fmaxf(fmaf(a.x * ic, sc[c + 0], sh[c + 0]), 0.f);
                a.y = fmaxf(fmaf(a.y * ic, sc[c + 1], sh[c + 1]), 0.f);
                a.z = fmaxf(fmaf(a.z * ic, sc[c + 2], sh[c + 2]), 0.f);
                a.w = fmaxf(fmaf(a.w * ic, sc[c + 3], sh[c + 3]), 0.f);
            }
            xsv[i] = a;
        }
    }
    __syncthreads();

    const int tc = threadIdx.x % CG;
    const int tr = threadIdx.x / CG;

    u64 acc2[RPT][4];
#pragma unroll
    for (int r = 0; r < RPT; r++)
#pragma unroll
        for (int c = 0; c < 4; c++) acc2[r][c] = 0ULL;

#pragma unroll 2
    for (int kk2 = 0; kk2 < 32; kk2++) {
        u64 w00 = ws[(2 * kk2) * C + tc];
        u64 w01 = ws[(2 * kk2) * C + tc + CG];
        u64 w02 = ws[(2 * kk2) * C + tc + 2 * CG];
        u64 w03 = ws[(2 * kk2) * C + tc + 3 * CG];
        u64 w10 = ws[(2 * kk2 + 1) * C + tc];
        u64 w11 = ws[(2 * kk2 + 1) * C + tc + CG];
        u64 w12 = ws[(2 * kk2 + 1) * C + tc + 2 * CG];
        u64 w13 = ws[(2 * kk2 + 1) * C + tc + 3 * CG];
#pragma unroll
        for (int r = 0; r < RPT; r++) {
            ulonglong2 xq = *reinterpret_cast<const ulonglong2*>(
                xs + (tr + r * RT) * 128 + 4 * kk2);
            fma2(acc2[r][0], xq.x, w00);
            fma2(acc2[r][1], xq.x, w01);
            fma2(acc2[r][2], xq.x, w02);
            fma2(acc2[r][3], xq.x, w03);
            fma2(acc2[r][0], xq.y, w10);
            fma2(acc2[r][1], xq.y, w11);
            fma2(acc2[r][2], xq.y, w12);
            fma2(acc2[r][3], xq.y, w13);
        }
    }

    float bv0 = __ldg(&bias[tc]);
    float bv1 = __ldg(&bias[tc + CG]);
    float bv2 = __ldg(&bias[tc + 2 * CG]);
    float bv3 = __ldg(&bias[tc + 3 * CG]);

#pragma unroll
    for (int r = 0; r < RPT; r++) {
        int row = row0 + tr + r * RT;
        float h0 = sum2(acc2[r][0]) + bv0;
        float h1 = sum2(acc2[r][1]) + bv1;
        float h2 = sum2(acc2[r][2]) + bv2;
        float h3 = sum2(acc2[r][3]) + bv3;
        if (RELU) {
            h0 = fmaxf(h0, 0.f); h1 = fmaxf(h1, 0.f);
            h2 = fmaxf(h2, 0.f); h3 = fmaxf(h3, 0.f);
        }
        if (CLS) {
            float p0 = h0 * __ldg(&Wc2[tc * 2])                + h1 * __ldg(&Wc2[(tc + CG) * 2])
                     + h2 * __ldg(&Wc2[(tc + 2 * CG) * 2])     + h3 * __ldg(&Wc2[(tc + 3 * CG) * 2]);
            float p1 = h0 * __ldg(&Wc2[tc * 2 + 1])            + h1 * __ldg(&Wc2[(tc + CG) * 2 + 1])
                     + h2 * __ldg(&Wc2[(tc + 2 * CG) * 2 + 1]) + h3 * __ldg(&Wc2[(tc + 3 * CG) * 2 + 1]);
#pragma unroll
            for (int o = CG / 2; o; o >>= 1) {
                p0 += __shfl_xor_sync(0xffffffffu, p0, o);
                p1 += __shfl_xor_sync(0xffffffffu, p1, o);
            }
            if (tc == 0 && row < NN) {
                outf[(size_t)row * 2 + 0] = p0 + bc2[0];
                outf[(size_t)row * 2 + 1] = p1 + bc2[1];
            }
        } else if (row < NN) {
            __half* orow = outh + (size_t)row * C;
            orow[tc]          = __float2half(h0);
            orow[tc + CG]     = __float2half(h1);
            orow[tc + 2 * CG] = __float2half(h2);
            orow[tc + 3 * CG] = __float2half(h3);
        }
    }
}

// ---------------------------------------------------------------------------
// pull aggregation: HALF-WARP per node (16 lanes x uint4 = 256 B fp16 row);
// 2 independent node chains per warp -> halved instruction count, 2x MLP.
// ---------------------------------------------------------------------------
__device__ __forceinline__ void acc8(float* a, uint4 u) {
    float2 f;
    f = __half22float2(*reinterpret_cast<__half2*>(&u.x)); a[0] += f.x; a[1] += f.y;
    f = __half22float2(*reinterpret_cast<__half2*>(&u.y)); a[2] += f.x; a[3] += f.y;
    f = __half22float2(*reinterpret_cast<__half2*>(&u.z)); a[4] += f.x; a[5] += f.y;
    f = __half22float2(*reinterpret_cast<__half2*>(&u.w)); a[6] += f.x; a[7] += f.y;
}

__global__ void __launch_bounds__(256) agg_k(const int* __restrict__ adj,
                                             const int* __restrict__ off,
                                             const __half* __restrict__ h,
                                             float* __restrict__ acc) {
    int node = (blockIdx.x * 256 + threadIdx.x) >> 4;   // half-warp id
    int lane = threadIdx.x & 15;
    if (node >= NN) return;

    int beg = __ldg(&off[node]);
    int end = __ldg(&off[node + 1]);

    const uint4* hv = reinterpret_cast<const uint4*>(h);   // 16 uint4 per row
    float a[8] = {0.f, 0.f, 0.f, 0.f, 0.f, 0.f, 0.f, 0.f};
    acc8(a, __ldg(&hv[(size_t)node * 16 + lane]));          // self loop

    int i = beg;
    for (; i + 4 <= end; i += 4) {
        int s0 = __ldg(&adj[i]);
        int s1 = __ldg(&adj[i + 1]);
        int s2 = __ldg(&adj[i + 2]);
        int s3 = __ldg(&adj[i + 3]);
        uint4 u0 = __ldg(&hv[(size_t)s0 * 16 + lane]);
        uint4 u1 = __ldg(&hv[(size_t)s1 * 16 + lane]);
        uint4 u2 = __ldg(&hv[(size_t)s2 * 16 + lane]);
        uint4 u3 = __ldg(&hv[(size_t)s3 * 16 + lane]);
        acc8(a, u0);
        acc8(a, u1);
        acc8(a, u2);
        acc8(a, u3);
    }
    for (; i < end; i++) {
        int s = __ldg(&adj[i]);
        acc8(a, __ldg(&hv[(size_t)s * 16 + lane]));
    }

    float4* av = reinterpret_cast<float4*>(acc + (size_t)node * 128 + lane * 8);
    av[0] = make_float4(a[0], a[1], a[2], a[3]);
    av[1] = make_float4(a[4], a[5], a[6], a[7]);
}

// ---------------------------------------------------------------------------
// launch
// ---------------------------------------------------------------------------
extern "C" void kernel_launch(void* const* d_in, const int* in_sizes, int n_in,
                              void* d_out, int out_size) {
    const float* x   = (const float*)d_in[0];
    const int*   ei  = (const int*)d_in[1];
    const float *W1 = (const float*)d_in[2],  *b1  = (const float*)d_in[3];
    const float *g1 = (const float*)d_in[4],  *be1 = (const float*)d_in[5];
    const float *m1 = (const float*)d_in[6],  *v1  = (const float*)d_in[7];
    const float *W2 = (const float*)d_in[8],  *b2  = (const float*)d_in[9];
    const float *g2 = (const float*)d_in[10], *be2 = (const float*)d_in[11];
    const float *m2 = (const float*)d_in[12], *v2  = (const float*)d_in[13];
    const float *Wc1 = (const float*)d_in[14], *bc1 = (const float*)d_in[15];
    const float *Wc2 = (const float*)d_in[16], *bc2 = (const float*)d_in[17];
    float* out = (float*)d_out;

    const int* src = ei;
    const int* dst = ei + EE;

    __half* hhb;
    float* ab;
    int *degb, *offb, *curb, *adjb;
    cudaGetSymbolAddress((void**)&hhb, g_hh);
    cudaGetSymbolAddress((void**)&ab, g_acc);
    cudaGetSymbolAddress((void**)&degb, g_deg);
    cudaGetSymbolAddress((void**)&offb, g_off);
    cudaGetSymbolAddress((void**)&curb, g_cur);
    cudaGetSymbolAddress((void**)&adjb, g_adj);

    const int GB = (NN + 63) / 64;
    const int AB = (NN * 16 + 255) / 256;   // half-warp per node

    const int SM128 = 64 * 128 * 4 + 64 * 128 * 8 + 1024;  // 99328
    const int SM64  = 64 * 128 * 4 + 64 * 64 * 8 + 1024;   // 66560

    cudaFuncSetAttribute(gemm_k<128, false, false, false>,
                         cudaFuncAttributeMaxDynamicSharedMemorySize, SM128);
    cudaFuncSetAttribute(gemm_k<128, false, true, false>,
                         cudaFuncAttributeMaxDynamicSharedMemorySize, SM128);
    cudaFuncSetAttribute(gemm_k<64, true, true, true>,
                         cudaFuncAttributeMaxDynamicSharedMemorySize, SM64);

    // CSR build (deg pre-zeroed: static init on first run, scan_k re-zeroes after)
    deg_k<<<(EE + 255) / 256, 256>>>(dst, degb);
    scan_k<<<1, SCAN_T>>>(degb, offb, curb);
    fill_k<<<(EE + 255) / 256, 256>>>(src, dst, curb, adjb);

    // layer 1  (launch #4 -> profiled)
    gemm_k<128, false, false, false><<<GB, 256, SM128>>>(x, W1, b1, hhb, nullptr,
        nullptr, nullptr, nullptr, nullptr, nullptr, nullptr, nullptr);
    agg_k<<<AB, 256>>>(adjb, offb, hhb, ab);

    // layer 2 (finalize of layer 1 fused into GEMM input)
    gemm_k<128, false, true, false><<<GB, 256, SM128>>>(ab, W2, b2, hhb, nullptr,
        offb, g1, be1, m1, v1, nullptr, nullptr);
    agg_k<<<AB, 256>>>(adjb, offb, hhb, ab);

    // classifier (finalize of layer 2 + Wc1 GEMM + Wc2 tail fused)
    gemm_k<64, true, true, true><<<GB, 256, SM64>>>(ab, Wc1, bc1, nullptr, out,
        offb, g2, be2, m2, v2, Wc2, bc2);
}